// round 1
// baseline (speedup 1.0000x reference)
#include <cuda_runtime.h>
#include <math.h>

#define B_  2
#define L_  2048
#define D_  512
#define H_  8
#define HD_ 64

// Scratch (device globals: no allocation in kernel_launch, per harness rules)
__device__ float g_qh[(size_t)B_ * H_ * L_ * D_];
__device__ float g_kh[(size_t)B_ * H_ * L_ * D_];
__device__ float g_vh[(size_t)B_ * H_ * L_ * D_];
__device__ float g_ctx[(size_t)B_ * H_ * L_ * D_];
__device__ float g_comb[(size_t)B_ * L_ * H_ * D_];

// ---------------------------------------------------------------------------
// Generic batched 128x128x16 fp32 tiled GEMM.
// BTRANS=1: C[m,n] = alpha * sum_k A[m,k] * B[n,k]   (both row-major, K-major)
// BTRANS=0: C[m,n] = alpha * sum_k A[m,k] * B[k,n]   (B row-major ld N)
// Batch z: Ab = A + (z/adiv)*sA ; Bb = B + (z%bmod)*sB ; Cb = C + z*sC
// Requires: M%128==0, N%128==0, K%16==0, all pointers 16B aligned.
// ---------------------------------------------------------------------------
template <int BTRANS>
__global__ __launch_bounds__(256)
void gemm128(const float* __restrict__ A, const float* __restrict__ Bm,
             float* __restrict__ C,
             int M, int N, int K,
             long sA, long sB, long sC,
             int adiv, int bmod, float alpha)
{
    __shared__ float As[16][128];
    __shared__ float Bs[16][128];

    const int z = blockIdx.z;
    const float* Ab = A + (long)(z / adiv) * sA;
    const float* Bb = Bm + (long)(z % bmod) * sB;
    float* Cb = C + (long)z * sC;

    const int m0 = blockIdx.y * 128;
    const int n0 = blockIdx.x * 128;
    const int tid = threadIdx.x;
    const int tx = tid & 15;   // 0..15 -> n sub-tile
    const int ty = tid >> 4;   // 0..15 -> m sub-tile

    float acc[8][8];
#pragma unroll
    for (int i = 0; i < 8; i++)
#pragma unroll
        for (int j = 0; j < 8; j++) acc[i][j] = 0.f;

    for (int k0 = 0; k0 < K; k0 += 16) {
        // ---- load A tile (128 x 16), store transposed As[k][m] ----
#pragma unroll
        for (int it = 0; it < 2; it++) {
            int idx = tid + it * 256;       // 0..511
            int row = idx >> 2;             // 0..127
            int kf  = (idx & 3) << 2;       // 0,4,8,12
            float4 va = *(const float4*)(Ab + (long)(m0 + row) * K + (k0 + kf));
            As[kf + 0][row] = va.x;
            As[kf + 1][row] = va.y;
            As[kf + 2][row] = va.z;
            As[kf + 3][row] = va.w;
            if (BTRANS) {
                float4 vb = *(const float4*)(Bb + (long)(n0 + row) * K + (k0 + kf));
                Bs[kf + 0][row] = vb.x;
                Bs[kf + 1][row] = vb.y;
                Bs[kf + 2][row] = vb.z;
                Bs[kf + 3][row] = vb.w;
            } else {
                int kk = idx >> 5;          // 0..15
                int nf = (idx & 31) << 2;   // 0..124
                float4 vb = *(const float4*)(Bb + (long)(k0 + kk) * N + (n0 + nf));
                *(float4*)&Bs[kk][nf] = vb;
            }
        }
        __syncthreads();

#pragma unroll
        for (int k = 0; k < 16; k++) {
            float4 a0 = *(const float4*)&As[k][ty * 8];
            float4 a1 = *(const float4*)&As[k][ty * 8 + 4];
            float4 b0 = *(const float4*)&Bs[k][tx * 8];
            float4 b1 = *(const float4*)&Bs[k][tx * 8 + 4];
            float a[8] = {a0.x, a0.y, a0.z, a0.w, a1.x, a1.y, a1.z, a1.w};
            float b[8] = {b0.x, b0.y, b0.z, b0.w, b1.x, b1.y, b1.z, b1.w};
#pragma unroll
            for (int i = 0; i < 8; i++)
#pragma unroll
                for (int j = 0; j < 8; j++) acc[i][j] += a[i] * b[j];
        }
        __syncthreads();
    }

    // ---- epilogue ----
#pragma unroll
    for (int i = 0; i < 8; i++) {
        long coff = (long)(m0 + ty * 8 + i) * N + n0 + tx * 8;
        float4 o0, o1;
        o0.x = alpha * acc[i][0]; o0.y = alpha * acc[i][1];
        o0.z = alpha * acc[i][2]; o0.w = alpha * acc[i][3];
        o1.x = alpha * acc[i][4]; o1.y = alpha * acc[i][5];
        o1.z = alpha * acc[i][6]; o1.w = alpha * acc[i][7];
        *(float4*)(Cb + coff)     = o0;
        *(float4*)(Cb + coff + 4) = o1;
    }
}

// ---------------------------------------------------------------------------
// Row softmax, ncols = 2048, in place. One block (256 threads) per row.
// ---------------------------------------------------------------------------
__global__ __launch_bounds__(256)
void softmax_rows(float* __restrict__ data)
{
    const int NC = 2048;
    float* p = data + (long)blockIdx.x * NC;
    const int tid = threadIdx.x;

    float vals[8];
    float vmax = -1e30f;
#pragma unroll
    for (int i = 0; i < 8; i++) {
        vals[i] = p[tid + i * 256];
        vmax = fmaxf(vmax, vals[i]);
    }
#pragma unroll
    for (int o = 16; o > 0; o >>= 1)
        vmax = fmaxf(vmax, __shfl_xor_sync(0xFFFFFFFFu, vmax, o));

    __shared__ float smax[8];
    __shared__ float ssum[8];
    if ((tid & 31) == 0) smax[tid >> 5] = vmax;
    __syncthreads();
    float m = smax[0];
#pragma unroll
    for (int i = 1; i < 8; i++) m = fmaxf(m, smax[i]);

    float sum = 0.f;
#pragma unroll
    for (int i = 0; i < 8; i++) {
        vals[i] = __expf(vals[i] - m);
        sum += vals[i];
    }
#pragma unroll
    for (int o = 16; o > 0; o >>= 1)
        sum += __shfl_xor_sync(0xFFFFFFFFu, sum, o);
    if ((tid & 31) == 0) ssum[tid >> 5] = sum;
    __syncthreads();
    float tot = 0.f;
#pragma unroll
    for (int i = 0; i < 8; i++) tot += ssum[i];
    float inv = 1.f / tot;
#pragma unroll
    for (int i = 0; i < 8; i++) p[tid + i * 256] = vals[i] * inv;
}

// ---------------------------------------------------------------------------
// comb[b,l, h2*512 + h1*64 + hd] = ctx[b,h1,l, h2*64 + hd]
// ---------------------------------------------------------------------------
__global__ __launch_bounds__(256)
void build_comb(const float* __restrict__ ctx, float* __restrict__ comb)
{
    long idx = (long)blockIdx.x * blockDim.x + threadIdx.x;   // over B*L*H*D
    int j = (int)(idx & (H_ * D_ - 1));      // H*D = 4096, power of 2
    long bl = idx >> 12;                      // /4096
    int b = (int)(bl >> 11);                  // /2048
    int l = (int)(bl & (L_ - 1));
    int h2 = j >> 9;                          // /512
    int rest = j & 511;
    int h1 = rest >> 6;
    int hd = rest & 63;
    comb[idx] = ctx[(((long)(b * H_ + h1) * L_ + l) * D_) + h2 * HD_ + hd];
}

// ---------------------------------------------------------------------------
extern "C" void kernel_launch(void* const* d_in, const int* in_sizes, int n_in,
                              void* d_out, int out_size)
{
    const float* q  = (const float*)d_in[0];
    const float* k  = (const float*)d_in[1];
    const float* v  = (const float*)d_in[2];
    const float* Wq = (const float*)d_in[3];
    const float* Wk = (const float*)d_in[4];
    const float* Wv = (const float*)d_in[5];
    const float* Wo = (const float*)d_in[6];

    float* out  = (float*)d_out;                       // [B,L,D]
    float* attn = out + (long)B_ * L_ * D_;            // [B,H,L,L]

    float *qh, *kh, *vh, *ctx, *comb;
    cudaGetSymbolAddress((void**)&qh,   g_qh);
    cudaGetSymbolAddress((void**)&kh,   g_kh);
    cudaGetSymbolAddress((void**)&vh,   g_vh);
    cudaGetSymbolAddress((void**)&ctx,  g_ctx);
    cudaGetSymbolAddress((void**)&comb, g_comb);

    const long sLD = (long)L_ * D_;
    const long sLL = (long)L_ * L_;
    const long sDD = (long)D_ * D_;
    const float inv_sqrt_d = 1.0f / sqrtf((float)D_);

    dim3 blk(256);

    // 1) projections: per (b,h): [L,D] @ W[h]^T -> [L,D]
    dim3 gproj(D_ / 128, L_ / 128, B_ * H_);
    gemm128<1><<<gproj, blk>>>(q, Wq, qh, L_, D_, D_, sLD, sDD, sLD, H_, H_, 1.0f);
    gemm128<1><<<gproj, blk>>>(k, Wk, kh, L_, D_, D_, sLD, sDD, sLD, H_, H_, 1.0f);
    gemm128<1><<<gproj, blk>>>(v, Wv, vh, L_, D_, D_, sLD, sDD, sLD, H_, H_, 1.0f);

    // 2) scores -> attn region of d_out: qh @ kh^T / sqrt(D)
    dim3 gsc(L_ / 128, L_ / 128, B_ * H_);
    gemm128<1><<<gsc, blk>>>(qh, kh, attn, L_, L_, D_, sLD, sLD, sLL,
                             1, 1 << 20, inv_sqrt_d);

    // 3) softmax in place over last dim
    softmax_rows<<<B_ * H_ * L_, blk>>>(attn);

    // 4) ctx = attn @ vh   (NN)
    dim3 gctx(D_ / 128, L_ / 128, B_ * H_);
    gemm128<0><<<gctx, blk>>>(attn, vh, ctx, L_, D_, L_, sLL, sLD, sLD,
                              1, 1 << 20, 1.0f);

    // 5) comb permute
    long ncomb = (long)B_ * L_ * H_ * D_;
    build_comb<<<(unsigned)(ncomb / 256), blk>>>(ctx, comb);

    // 6) out = comb @ Wo^T : [B*L, H*D] x [D, H*D]^T
    dim3 gout(D_ / 128, (B_ * L_) / 128, 1);
    gemm128<1><<<gout, blk>>>(comb, Wo, out, B_ * L_, D_, H_ * D_,
                              0, 1, 0 + (long)B_ * L_ * D_ * 0, 1, 1 << 20, 1.0f);
}

// round 3
// speedup vs baseline: 2.5846x; 2.5846x over previous
#include <cuda_runtime.h>
#include <cuda_bf16.h>
#include <stdint.h>
#include <math.h>

#define B_  2
#define L_  2048
#define D_  512
#define H_  8
#define HD_ 64

// ======================= scratch (device globals) ==========================
__device__ __nv_bfloat16 g_q_hi [(size_t)B_*L_*D_];
__device__ __nv_bfloat16 g_q_lo [(size_t)B_*L_*D_];
__device__ __nv_bfloat16 g_k_hi [(size_t)B_*L_*D_];
__device__ __nv_bfloat16 g_k_lo [(size_t)B_*L_*D_];
__device__ __nv_bfloat16 g_v_hi [(size_t)B_*L_*D_];
__device__ __nv_bfloat16 g_v_lo [(size_t)B_*L_*D_];
__device__ __nv_bfloat16 g_Wq_hi[(size_t)H_*D_*D_];
__device__ __nv_bfloat16 g_Wq_lo[(size_t)H_*D_*D_];
__device__ __nv_bfloat16 g_Wk_hi[(size_t)H_*D_*D_];
__device__ __nv_bfloat16 g_Wk_lo[(size_t)H_*D_*D_];
__device__ __nv_bfloat16 g_Wv_hi[(size_t)H_*D_*D_];
__device__ __nv_bfloat16 g_Wv_lo[(size_t)H_*D_*D_];
__device__ __nv_bfloat16 g_Wo_hi[(size_t)D_*H_*D_];
__device__ __nv_bfloat16 g_Wo_lo[(size_t)D_*H_*D_];
__device__ __nv_bfloat16 g_qh_hi[(size_t)B_*H_*L_*D_];
__device__ __nv_bfloat16 g_qh_lo[(size_t)B_*H_*L_*D_];
__device__ __nv_bfloat16 g_kh_hi[(size_t)B_*H_*L_*D_];
__device__ __nv_bfloat16 g_kh_lo[(size_t)B_*H_*L_*D_];
__device__ __nv_bfloat16 g_vT_hi[(size_t)B_*H_*D_*L_];
__device__ __nv_bfloat16 g_vT_lo[(size_t)B_*H_*D_*L_];
__device__ __nv_bfloat16 g_at_hi[(size_t)B_*H_*L_*L_];
__device__ __nv_bfloat16 g_at_lo[(size_t)B_*H_*L_*L_];
__device__ __nv_bfloat16 g_cb_hi[(size_t)B_*L_*H_*D_];
__device__ __nv_bfloat16 g_cb_lo[(size_t)B_*L_*H_*D_];
__device__ float         g_vh  [(size_t)B_*H_*L_*D_];
__device__ float         g_ctx [(size_t)B_*H_*L_*D_];

// ======================= small helpers ======================================
__device__ __forceinline__ uint32_t smem_u32(const void* p) {
    uint32_t a;
    asm("{ .reg .u64 t; cvta.to.shared.u64 t, %1; cvt.u32.u64 %0, t; }"
        : "=r"(a) : "l"(p));
    return a;
}
// SW64-style swizzle for 64-byte rows: conflict-free ldmatrix + stores
__device__ __forceinline__ uint32_t swz(uint32_t o) { return o ^ ((o >> 3) & 0x30); }

__device__ __forceinline__ void cp16(uint32_t s, const void* g) {
    asm volatile("cp.async.cg.shared.global [%0], [%1], 16;" :: "r"(s), "l"(g));
}
#define CP_COMMIT() asm volatile("cp.async.commit_group;" ::: "memory")

__device__ __forceinline__ void ldm4(uint32_t* r, uint32_t a) {
    asm volatile("ldmatrix.sync.aligned.m8n8.x4.shared.b16 {%0,%1,%2,%3}, [%4];"
                 : "=r"(r[0]), "=r"(r[1]), "=r"(r[2]), "=r"(r[3]) : "r"(a));
}
__device__ __forceinline__ void mma_bf16(float* c, const uint32_t* a, const uint32_t* b) {
    asm volatile("mma.sync.aligned.m16n8k16.row.col.f32.bf16.bf16.f32 "
                 "{%0,%1,%2,%3}, {%4,%5,%6,%7}, {%8,%9}, {%0,%1,%2,%3};"
                 : "+f"(c[0]), "+f"(c[1]), "+f"(c[2]), "+f"(c[3])
                 : "r"(a[0]), "r"(a[1]), "r"(a[2]), "r"(a[3]), "r"(b[0]), "r"(b[1]));
}
__device__ __forceinline__ void split2(float x, __nv_bfloat16& h, __nv_bfloat16& l) {
    h = __float2bfloat16(x);
    l = __float2bfloat16(x - __bfloat162float(h));
}

// ======================= bf16x3 HMMA GEMM ===================================
// C[m,n] = alpha * sum_k A[m,k]*B[n,k]   (NT, both K-major bf16 hi/lo)
// MODE 0: fp32 C out.  MODE 1: bf16 hi/lo out.
#define KC       32
#define TILE_B   (128 * 64)        // one operand tile: 128 rows x 64B (32 bf16)
#define STAGE_B  (4 * TILE_B)      // Ah, Al, Bh, Bl = 32 KB
#define SMEM_T   (2 * STAGE_B)     // 64 KB double-buffered

template <int MODE>
__global__ __launch_bounds__(256, 1)
void mma_gemm(const __nv_bfloat16* __restrict__ Ahi, const __nv_bfloat16* __restrict__ Alo,
              const __nv_bfloat16* __restrict__ Bhi, const __nv_bfloat16* __restrict__ Blo,
              float* __restrict__ C, __nv_bfloat16* __restrict__ Chi,
              __nv_bfloat16* __restrict__ Clo,
              int N, int K, long sA, long sB, long sC,
              int adiv, int bmod, float alpha)
{
    extern __shared__ char smem[];
    const uint32_t sb = smem_u32(smem);
    const int tid  = threadIdx.x;
    const int lane = tid & 31, wid = tid >> 5;
    const int moff = (wid & 1) * 64;      // warp M offset (2 warps over 128)
    const int noff = (wid >> 1) * 32;     // warp N offset (4 warps over 128)

    const int z = blockIdx.z;
    const __nv_bfloat16* A0h = Ahi + (long)(z / adiv) * sA;
    const __nv_bfloat16* A0l = Alo + (long)(z / adiv) * sA;
    const __nv_bfloat16* B0h = Bhi + (long)(z % bmod) * sB;
    const __nv_bfloat16* B0l = Blo + (long)(z % bmod) * sB;
    const long coff = (long)z * sC;
    const long m0 = (long)blockIdx.y * 128;
    const long n0 = (long)blockIdx.x * 128;

    float acc[4][4][4];
#pragma unroll
    for (int a = 0; a < 4; a++)
#pragma unroll
        for (int b = 0; b < 4; b++)
#pragma unroll
            for (int c = 0; c < 4; c++) acc[a][b][c] = 0.f;

    const int NC = K / KC;

    // per-thread load slots: idx over 512 16B-chunks per tile
    const int r0 = tid >> 2, c0 = tid & 3;           // slot 0
    const int r1 = (tid + 256) >> 2, c1 = tid & 3;   // slot 1

#define LOAD_STAGE(cidx) do {                                                   \
        const uint32_t st = sb + ((cidx) & 1) * STAGE_B;                        \
        const int k0 = (cidx) * KC;                                             \
        const long goA0 = (m0 + r0) * (long)K + k0 + c0 * 8;                    \
        const long goA1 = (m0 + r1) * (long)K + k0 + c1 * 8;                    \
        const long goB0 = (n0 + r0) * (long)K + k0 + c0 * 8;                    \
        const long goB1 = (n0 + r1) * (long)K + k0 + c1 * 8;                    \
        const uint32_t so0 = swz(r0 * 64 + c0 * 16);                            \
        const uint32_t so1 = swz(r1 * 64 + c1 * 16);                            \
        cp16(st + so0,              A0h + goA0);                                \
        cp16(st + so1,              A0h + goA1);                                \
        cp16(st + TILE_B + so0,     A0l + goA0);                                \
        cp16(st + TILE_B + so1,     A0l + goA1);                                \
        cp16(st + 2 * TILE_B + so0, B0h + goB0);                                \
        cp16(st + 2 * TILE_B + so1, B0h + goB1);                                \
        cp16(st + 3 * TILE_B + so0, B0l + goB0);                                \
        cp16(st + 3 * TILE_B + so1, B0l + goB1);                                \
    } while (0)

    LOAD_STAGE(0);
    CP_COMMIT();

    // ldmatrix per-lane row/chunk patterns
    const int arow = (lane & 7) + ((lane >> 3) & 1) * 8;
    const int ach  = (lane >> 4);                    // + kk*2
    const int brow = (lane & 7) + ((lane >> 4) & 1) * 8;
    const int bch  = ((lane >> 3) & 1);              // + kk*2

    for (int c = 0; c < NC; c++) {
        if (c + 1 < NC) {
            LOAD_STAGE(c + 1);
            CP_COMMIT();
            asm volatile("cp.async.wait_group 1;" ::: "memory");
        } else {
            asm volatile("cp.async.wait_group 0;" ::: "memory");
        }
        __syncthreads();

        const uint32_t st = sb + (c & 1) * STAGE_B;
#pragma unroll
        for (int kk = 0; kk < 2; kk++) {
            uint32_t ah[4][4], al[4][4], bh[4][2], bl[4][2];
#pragma unroll
            for (int mf = 0; mf < 4; mf++) {
                uint32_t ad = st + swz((moff + mf * 16 + arow) * 64 + (kk * 2 + ach) * 16);
                ldm4(ah[mf], ad);
                ldm4(al[mf], ad + TILE_B);
            }
#pragma unroll
            for (int p = 0; p < 2; p++) {
                uint32_t bd = st + 2 * TILE_B +
                              swz((noff + p * 16 + brow) * 64 + (kk * 2 + bch) * 16);
                uint32_t r[4];
                ldm4(r, bd);
                bh[2 * p][0] = r[0]; bh[2 * p][1] = r[1];
                bh[2 * p + 1][0] = r[2]; bh[2 * p + 1][1] = r[3];
                ldm4(r, bd + TILE_B);
                bl[2 * p][0] = r[0]; bl[2 * p][1] = r[1];
                bl[2 * p + 1][0] = r[2]; bl[2 * p + 1][1] = r[3];
            }
#pragma unroll
            for (int mf = 0; mf < 4; mf++)
#pragma unroll
                for (int nf = 0; nf < 4; nf++) {
                    mma_bf16(acc[mf][nf], ah[mf], bh[nf]);
                    mma_bf16(acc[mf][nf], ah[mf], bl[nf]);
                    mma_bf16(acc[mf][nf], al[mf], bh[nf]);
                }
        }
        __syncthreads();
    }
#undef LOAD_STAGE

    // ---- epilogue ----
    const int gq = lane >> 2, tg = lane & 3;
#pragma unroll
    for (int mf = 0; mf < 4; mf++)
#pragma unroll
        for (int nf = 0; nf < 4; nf++) {
            const long row = m0 + moff + mf * 16 + gq;
            const long col = n0 + noff + nf * 8 + tg * 2;
            float v0 = alpha * acc[mf][nf][0];
            float v1 = alpha * acc[mf][nf][1];
            float v2 = alpha * acc[mf][nf][2];
            float v3 = alpha * acc[mf][nf][3];
            if (MODE == 0) {
                float2 p0 = {v0, v1}, p1 = {v2, v3};
                *reinterpret_cast<float2*>(C + coff + row * N + col)       = p0;
                *reinterpret_cast<float2*>(C + coff + (row + 8) * N + col) = p1;
            } else {
                __nv_bfloat16 h0, l0, h1, l1, h2, l2, h3, l3;
                split2(v0, h0, l0); split2(v1, h1, l1);
                split2(v2, h2, l2); split2(v3, h3, l3);
                uint32_t hp0 = (uint32_t)__bfloat16_as_ushort(h1) << 16 | __bfloat16_as_ushort(h0);
                uint32_t lp0 = (uint32_t)__bfloat16_as_ushort(l1) << 16 | __bfloat16_as_ushort(l0);
                uint32_t hp1 = (uint32_t)__bfloat16_as_ushort(h3) << 16 | __bfloat16_as_ushort(h2);
                uint32_t lp1 = (uint32_t)__bfloat16_as_ushort(l3) << 16 | __bfloat16_as_ushort(l2);
                *reinterpret_cast<uint32_t*>(Chi + coff + row * N + col)       = hp0;
                *reinterpret_cast<uint32_t*>(Clo + coff + row * N + col)       = lp0;
                *reinterpret_cast<uint32_t*>(Chi + coff + (row + 8) * N + col) = hp1;
                *reinterpret_cast<uint32_t*>(Clo + coff + (row + 8) * N + col) = lp1;
            }
        }
}

// ======================= helper kernels =====================================
__global__ __launch_bounds__(256)
void split_arr(const float4* __restrict__ s, uint2* __restrict__ hi,
               uint2* __restrict__ lo, int n4)
{
    int i = blockIdx.x * 256 + threadIdx.x;
    if (i >= n4) return;
    float4 v = s[i];
    __nv_bfloat16 h[4], l[4];
    split2(v.x, h[0], l[0]);
    split2(v.y, h[1], l[1]);
    split2(v.z, h[2], l[2]);
    split2(v.w, h[3], l[3]);
    hi[i] = *reinterpret_cast<uint2*>(h);
    lo[i] = *reinterpret_cast<uint2*>(l);
}

// vh [z][L][D] fp32 -> vhT hi/lo [z][D][L] bf16
__global__ __launch_bounds__(256)
void transpose_split(const float* __restrict__ src,
                     __nv_bfloat16* __restrict__ hi, __nv_bfloat16* __restrict__ lo)
{
    __shared__ float t[32][33];
    const int z = blockIdx.z;
    const int l0 = blockIdx.y * 32, d0 = blockIdx.x * 32;
    const int tx = threadIdx.x & 31, ty = threadIdx.x >> 5;  // 32x8
    const float* s = src + (long)z * L_ * D_;
#pragma unroll
    for (int r = 0; r < 32; r += 8)
        t[ty + r][tx] = s[(long)(l0 + ty + r) * D_ + d0 + tx];
    __syncthreads();
    const long base = (long)z * D_ * L_;
#pragma unroll
    for (int r = 0; r < 32; r += 8) {
        float x = t[tx][ty + r];
        __nv_bfloat16 h, l;
        split2(x, h, l);
        long o = base + (long)(d0 + ty + r) * L_ + l0 + tx;
        hi[o] = h; lo[o] = l;
    }
}

// softmax over rows of 2048, in place (fp32) + bf16 hi/lo split outputs
__global__ __launch_bounds__(256)
void softmax_split(float* __restrict__ data,
                   __nv_bfloat16* __restrict__ hi, __nv_bfloat16* __restrict__ lo)
{
    const long rb = (long)blockIdx.x * 2048;
    float* p = data + rb;
    const int tid = threadIdx.x;

    float vals[8];
    float vmax = -1e30f;
#pragma unroll
    for (int i = 0; i < 8; i++) { vals[i] = p[tid + i * 256]; vmax = fmaxf(vmax, vals[i]); }
#pragma unroll
    for (int o = 16; o > 0; o >>= 1) vmax = fmaxf(vmax, __shfl_xor_sync(0xFFFFFFFFu, vmax, o));

    __shared__ float smax[8], ssum[8];
    if ((tid & 31) == 0) smax[tid >> 5] = vmax;
    __syncthreads();
    float m = smax[0];
#pragma unroll
    for (int i = 1; i < 8; i++) m = fmaxf(m, smax[i]);

    float sum = 0.f;
#pragma unroll
    for (int i = 0; i < 8; i++) { vals[i] = __expf(vals[i] - m); sum += vals[i]; }
#pragma unroll
    for (int o = 16; o > 0; o >>= 1) sum += __shfl_xor_sync(0xFFFFFFFFu, sum, o);
    if ((tid & 31) == 0) ssum[tid >> 5] = sum;
    __syncthreads();
    float tot = 0.f;
#pragma unroll
    for (int i = 0; i < 8; i++) tot += ssum[i];
    const float inv = 1.f / tot;
#pragma unroll
    for (int i = 0; i < 8; i++) {
        float y = vals[i] * inv;
        p[tid + i * 256] = y;
        __nv_bfloat16 h, l;
        split2(y, h, l);
        hi[rb + tid + i * 256] = h;
        lo[rb + tid + i * 256] = l;
    }
}

// comb[b,l, h2*512 + h1*64 + hd] = ctx[b,h1,l, h2*64+hd], split to hi/lo
__global__ __launch_bounds__(256)
void build_comb_split(const float* __restrict__ ctx,
                      __nv_bfloat16* __restrict__ hi, __nv_bfloat16* __restrict__ lo)
{
    long idx = (long)blockIdx.x * 256 + threadIdx.x;
    int j = (int)(idx & (H_ * D_ - 1));
    long bl = idx >> 12;
    int b = (int)(bl >> 11);
    int l = (int)(bl & (L_ - 1));
    int h2 = j >> 9;
    int rest = j & 511;
    int h1 = rest >> 6;
    int hd = rest & 63;
    float x = ctx[(((long)(b * H_ + h1) * L_ + l) * D_) + h2 * HD_ + hd];
    __nv_bfloat16 h, lw;
    split2(x, h, lw);
    hi[idx] = h; lo[idx] = lw;
}

// ======================= launch =============================================
extern "C" void kernel_launch(void* const* d_in, const int* in_sizes, int n_in,
                              void* d_out, int out_size)
{
    const float* q  = (const float*)d_in[0];
    const float* k  = (const float*)d_in[1];
    const float* v  = (const float*)d_in[2];
    const float* Wq = (const float*)d_in[3];
    const float* Wk = (const float*)d_in[4];
    const float* Wv = (const float*)d_in[5];
    const float* Wo = (const float*)d_in[6];

    float* out  = (float*)d_out;
    float* attn = out + (long)B_ * L_ * D_;

    static bool attr_done = false;
    if (!attr_done) {
        cudaFuncSetAttribute(mma_gemm<0>, cudaFuncAttributeMaxDynamicSharedMemorySize, SMEM_T);
        cudaFuncSetAttribute(mma_gemm<1>, cudaFuncAttributeMaxDynamicSharedMemorySize, SMEM_T);
        attr_done = true;
    }

#define SYM(p, s) cudaGetSymbolAddress((void**)&p, s)
    __nv_bfloat16 *q_hi, *q_lo, *k_hi, *k_lo, *v_hi, *v_lo;
    __nv_bfloat16 *Wq_hi, *Wq_lo, *Wk_hi, *Wk_lo, *Wv_hi, *Wv_lo, *Wo_hi, *Wo_lo;
    __nv_bfloat16 *qh_hi, *qh_lo, *kh_hi, *kh_lo, *vT_hi, *vT_lo;
    __nv_bfloat16 *at_hi, *at_lo, *cb_hi, *cb_lo;
    float *vh, *ctx;
    SYM(q_hi, g_q_hi);  SYM(q_lo, g_q_lo);
    SYM(k_hi, g_k_hi);  SYM(k_lo, g_k_lo);
    SYM(v_hi, g_v_hi);  SYM(v_lo, g_v_lo);
    SYM(Wq_hi, g_Wq_hi); SYM(Wq_lo, g_Wq_lo);
    SYM(Wk_hi, g_Wk_hi); SYM(Wk_lo, g_Wk_lo);
    SYM(Wv_hi, g_Wv_hi); SYM(Wv_lo, g_Wv_lo);
    SYM(Wo_hi, g_Wo_hi); SYM(Wo_lo, g_Wo_lo);
    SYM(qh_hi, g_qh_hi); SYM(qh_lo, g_qh_lo);
    SYM(kh_hi, g_kh_hi); SYM(kh_lo, g_kh_lo);
    SYM(vT_hi, g_vT_hi); SYM(vT_lo, g_vT_lo);
    SYM(at_hi, g_at_hi); SYM(at_lo, g_at_lo);
    SYM(cb_hi, g_cb_hi); SYM(cb_lo, g_cb_lo);
    SYM(vh, g_vh); SYM(ctx, g_ctx);
#undef SYM

    const long sLD = (long)L_ * D_;
    const long sLL = (long)L_ * L_;
    const long sDD = (long)D_ * D_;
    const long sDL = (long)D_ * L_;
    const float inv_sqrt_d = 1.0f / sqrtf((float)D_);

    dim3 blk(256);
    const int n4_in = (B_ * L_ * D_) / 4;
    const int n4_w  = (H_ * D_ * D_) / 4;

    // 0) split inputs to bf16 hi/lo
    split_arr<<<(n4_in + 255) / 256, blk>>>((const float4*)q, (uint2*)q_hi, (uint2*)q_lo, n4_in);
    split_arr<<<(n4_in + 255) / 256, blk>>>((const float4*)k, (uint2*)k_hi, (uint2*)k_lo, n4_in);
    split_arr<<<(n4_in + 255) / 256, blk>>>((const float4*)v, (uint2*)v_hi, (uint2*)v_lo, n4_in);
    split_arr<<<(n4_w + 255) / 256, blk>>>((const float4*)Wq, (uint2*)Wq_hi, (uint2*)Wq_lo, n4_w);
    split_arr<<<(n4_w + 255) / 256, blk>>>((const float4*)Wk, (uint2*)Wk_hi, (uint2*)Wk_lo, n4_w);
    split_arr<<<(n4_w + 255) / 256, blk>>>((const float4*)Wv, (uint2*)Wv_hi, (uint2*)Wv_lo, n4_w);
    split_arr<<<(n4_w + 255) / 256, blk>>>((const float4*)Wo, (uint2*)Wo_hi, (uint2*)Wo_lo, n4_w);

    // 1) projections: [L,D] @ W[h]^T, batch (b,h) = 16
    dim3 gproj(D_ / 128, L_ / 128, B_ * H_);
    mma_gemm<1><<<gproj, blk, SMEM_T>>>(q_hi, q_lo, Wq_hi, Wq_lo,
        nullptr, qh_hi, qh_lo, D_, D_, sLD, sDD, sLD, H_, H_, 1.0f);
    mma_gemm<1><<<gproj, blk, SMEM_T>>>(k_hi, k_lo, Wk_hi, Wk_lo,
        nullptr, kh_hi, kh_lo, D_, D_, sLD, sDD, sLD, H_, H_, 1.0f);
    mma_gemm<0><<<gproj, blk, SMEM_T>>>(v_hi, v_lo, Wv_hi, Wv_lo,
        vh, nullptr, nullptr, D_, D_, sLD, sDD, sLD, H_, H_, 1.0f);

    // 1b) vh -> vhT hi/lo
    dim3 gtr(D_ / 32, L_ / 32, B_ * H_);
    transpose_split<<<gtr, blk>>>(vh, vT_hi, vT_lo);

    // 2) scores = qh @ kh^T / sqrt(D) -> attn (fp32, in d_out)
    dim3 gsc(L_ / 128, L_ / 128, B_ * H_);
    mma_gemm<0><<<gsc, blk, SMEM_T>>>(qh_hi, qh_lo, kh_hi, kh_lo,
        attn, nullptr, nullptr, L_, D_, sLD, sLD, sLL, 1, B_ * H_, inv_sqrt_d);

    // 3) softmax in place + split to bf16 hi/lo
    softmax_split<<<B_ * H_ * L_, blk>>>(attn, at_hi, at_lo);

    // 4) ctx = attn @ vh  (NT vs vT)
    dim3 gctx(D_ / 128, L_ / 128, B_ * H_);
    mma_gemm<0><<<gctx, blk, SMEM_T>>>(at_hi, at_lo, vT_hi, vT_lo,
        ctx, nullptr, nullptr, D_, L_, sLL, sDL, sLD, 1, B_ * H_, 1.0f);

    // 5) comb permute + split
    long ncomb = (long)B_ * L_ * H_ * D_;
    build_comb_split<<<(unsigned)(ncomb / 256), blk>>>(ctx, cb_hi, cb_lo);

    // 6) out = comb @ Wo^T
    dim3 gout(D_ / 128, (B_ * L_) / 128, 1);
    mma_gemm<0><<<gout, blk, SMEM_T>>>(cb_hi, cb_lo, Wo_hi, Wo_lo,
        out, nullptr, nullptr, D_, H_ * D_, 0, 0, 0, 1, 1, 1.0f);
}

// round 4
// speedup vs baseline: 2.8319x; 1.0957x over previous
#include <cuda_runtime.h>
#include <cuda_bf16.h>
#include <stdint.h>
#include <math.h>

#define B_  2
#define L_  2048
#define D_  512
#define H_  8
#define HD_ 64

// ======================= scratch (device globals) ==========================
__device__ __nv_bfloat16 g_q_hi [(size_t)B_*L_*D_];
__device__ __nv_bfloat16 g_q_lo [(size_t)B_*L_*D_];
__device__ __nv_bfloat16 g_k_hi [(size_t)B_*L_*D_];
__device__ __nv_bfloat16 g_k_lo [(size_t)B_*L_*D_];
__device__ __nv_bfloat16 g_v_hi [(size_t)B_*L_*D_];
__device__ __nv_bfloat16 g_v_lo [(size_t)B_*L_*D_];
__device__ __nv_bfloat16 g_WqT_hi[(size_t)H_*D_*D_];
__device__ __nv_bfloat16 g_WqT_lo[(size_t)H_*D_*D_];
__device__ __nv_bfloat16 g_WkT_hi[(size_t)H_*D_*D_];
__device__ __nv_bfloat16 g_WkT_lo[(size_t)H_*D_*D_];
__device__ __nv_bfloat16 g_WvT_hi[(size_t)H_*D_*D_];
__device__ __nv_bfloat16 g_WvT_lo[(size_t)H_*D_*D_];
__device__ __nv_bfloat16 g_Wop_hi[(size_t)H_*D_*D_];
__device__ __nv_bfloat16 g_Wop_lo[(size_t)H_*D_*D_];
__device__ __nv_bfloat16 g_MT_hi[(size_t)H_*D_*D_];
__device__ __nv_bfloat16 g_MT_lo[(size_t)H_*D_*D_];
__device__ __nv_bfloat16 g_P_hi [(size_t)H_*D_*D_];
__device__ __nv_bfloat16 g_P_lo [(size_t)H_*D_*D_];
__device__ __nv_bfloat16 g_t_hi [(size_t)B_*H_*L_*D_];
__device__ __nv_bfloat16 g_t_lo [(size_t)B_*H_*L_*D_];
__device__ __nv_bfloat16 g_ZT_hi[(size_t)B_*D_*H_*L_];
__device__ __nv_bfloat16 g_ZT_lo[(size_t)B_*D_*H_*L_];
__device__ __nv_bfloat16 g_at_hi[(size_t)B_*L_*H_*L_];
__device__ __nv_bfloat16 g_at_lo[(size_t)B_*L_*H_*L_];

// ======================= small helpers ======================================
__device__ __forceinline__ uint32_t smem_u32(const void* p) {
    uint32_t a;
    asm("{ .reg .u64 t; cvta.to.shared.u64 t, %1; cvt.u32.u64 %0, t; }"
        : "=r"(a) : "l"(p));
    return a;
}
__device__ __forceinline__ uint32_t swz(uint32_t o) { return o ^ ((o >> 3) & 0x30); }

__device__ __forceinline__ void cp16(uint32_t s, const void* g) {
    asm volatile("cp.async.cg.shared.global [%0], [%1], 16;" :: "r"(s), "l"(g));
}
#define CP_COMMIT() asm volatile("cp.async.commit_group;" ::: "memory")

__device__ __forceinline__ void ldm4(uint32_t* r, uint32_t a) {
    asm volatile("ldmatrix.sync.aligned.m8n8.x4.shared.b16 {%0,%1,%2,%3}, [%4];"
                 : "=r"(r[0]), "=r"(r[1]), "=r"(r[2]), "=r"(r[3]) : "r"(a));
}
__device__ __forceinline__ void mma_bf16(float* c, const uint32_t* a, const uint32_t* b) {
    asm volatile("mma.sync.aligned.m16n8k16.row.col.f32.bf16.bf16.f32 "
                 "{%0,%1,%2,%3}, {%4,%5,%6,%7}, {%8,%9}, {%0,%1,%2,%3};"
                 : "+f"(c[0]), "+f"(c[1]), "+f"(c[2]), "+f"(c[3])
                 : "r"(a[0]), "r"(a[1]), "r"(a[2]), "r"(a[3]), "r"(b[0]), "r"(b[1]));
}
__device__ __forceinline__ void split2(float x, __nv_bfloat16& h, __nv_bfloat16& l) {
    h = __float2bfloat16(x);
    l = __float2bfloat16(x - __bfloat162float(h));
}

// ======================= bf16x3 HMMA GEMM (3-stage pipeline) ================
// C[m,n] = alpha * sum_k A[m,k]*B[n,k]   (NT, both K-major bf16 hi/lo)
// Batch z: Ab = A + ((z/adiv)%amod)*sA ; Bb = B + ((z/bdiv)%bmod)*sB
// C offset: coff = (z/czdiv)*sC1 + (z%czmod)*sC2 ; C row stride = ldc
// MODE 0: fp32 out. MODE 1: bf16 hi/lo out.
#define KC       32
#define TILE_B   (128 * 64)        // 128 rows x 64B (32 bf16)
#define STAGE_B  (4 * TILE_B)      // Ah, Al, Bh, Bl = 32 KB
#define NSTAGE   3
#define SMEM_T   (NSTAGE * STAGE_B) // 96 KB

template <int MODE>
__global__ __launch_bounds__(256, 1)
void mma_gemm(const __nv_bfloat16* __restrict__ Ahi, const __nv_bfloat16* __restrict__ Alo,
              const __nv_bfloat16* __restrict__ Bhi, const __nv_bfloat16* __restrict__ Blo,
              float* __restrict__ C, __nv_bfloat16* __restrict__ Chi,
              __nv_bfloat16* __restrict__ Clo,
              int K, int ldc, long sA, long sB,
              int adiv, int amod, int bdiv, int bmod,
              int czdiv, long sC1, int czmod, long sC2, float alpha)
{
    extern __shared__ char smem[];
    const uint32_t sb = smem_u32(smem);
    const int tid  = threadIdx.x;
    const int lane = tid & 31, wid = tid >> 5;
    const int moff = (wid & 1) * 64;
    const int noff = (wid >> 1) * 32;

    const int z = blockIdx.z;
    const __nv_bfloat16* A0h = Ahi + (long)((z / adiv) % amod) * sA;
    const __nv_bfloat16* A0l = Alo + (long)((z / adiv) % amod) * sA;
    const __nv_bfloat16* B0h = Bhi + (long)((z / bdiv) % bmod) * sB;
    const __nv_bfloat16* B0l = Blo + (long)((z / bdiv) % bmod) * sB;
    const long coff = (long)(z / czdiv) * sC1 + (long)(z % czmod) * sC2;
    const long m0 = (long)blockIdx.y * 128;
    const long n0 = (long)blockIdx.x * 128;

    float acc[4][4][4];
#pragma unroll
    for (int a = 0; a < 4; a++)
#pragma unroll
        for (int b = 0; b < 4; b++)
#pragma unroll
            for (int c = 0; c < 4; c++) acc[a][b][c] = 0.f;

    const int NC = K / KC;

    const int r0 = tid >> 2, c0 = tid & 3;
    const int r1 = (tid + 256) >> 2, c1 = tid & 3;

#define LOAD_STAGE(cidx) do {                                                   \
        const uint32_t st = sb + ((cidx) % NSTAGE) * STAGE_B;                   \
        const int k0 = (cidx) * KC;                                             \
        const long goA0 = (m0 + r0) * (long)K + k0 + c0 * 8;                    \
        const long goA1 = (m0 + r1) * (long)K + k0 + c1 * 8;                    \
        const long goB0 = (n0 + r0) * (long)K + k0 + c0 * 8;                    \
        const long goB1 = (n0 + r1) * (long)K + k0 + c1 * 8;                    \
        const uint32_t so0 = swz(r0 * 64 + c0 * 16);                            \
        const uint32_t so1 = swz(r1 * 64 + c1 * 16);                            \
        cp16(st + so0,              A0h + goA0);                                \
        cp16(st + so1,              A0h + goA1);                                \
        cp16(st + TILE_B + so0,     A0l + goA0);                                \
        cp16(st + TILE_B + so1,     A0l + goA1);                                \
        cp16(st + 2 * TILE_B + so0, B0h + goB0);                                \
        cp16(st + 2 * TILE_B + so1, B0h + goB1);                                \
        cp16(st + 3 * TILE_B + so0, B0l + goB0);                                \
        cp16(st + 3 * TILE_B + so1, B0l + goB1);                                \
    } while (0)

    LOAD_STAGE(0);
    CP_COMMIT();
    if (NC > 1) LOAD_STAGE(1);
    CP_COMMIT();

    const int arow = (lane & 7) + ((lane >> 3) & 1) * 8;
    const int ach  = (lane >> 4);
    const int brow = (lane & 7) + ((lane >> 4) & 1) * 8;
    const int bch  = ((lane >> 3) & 1);

    for (int c = 0; c < NC; c++) {
        asm volatile("cp.async.wait_group 1;" ::: "memory");
        __syncthreads();
        if (c + 2 < NC) LOAD_STAGE(c + 2);
        CP_COMMIT();

        const uint32_t st = sb + (c % NSTAGE) * STAGE_B;
#pragma unroll
        for (int kk = 0; kk < 2; kk++) {
            uint32_t ah[4][4], al[4][4], bh[4][2], bl[4][2];
#pragma unroll
            for (int mf = 0; mf < 4; mf++) {
                uint32_t ad = st + swz((moff + mf * 16 + arow) * 64 + (kk * 2 + ach) * 16);
                ldm4(ah[mf], ad);
                ldm4(al[mf], ad + TILE_B);
            }
#pragma unroll
            for (int p = 0; p < 2; p++) {
                uint32_t bd = st + 2 * TILE_B +
                              swz((noff + p * 16 + brow) * 64 + (kk * 2 + bch) * 16);
                uint32_t r[4];
                ldm4(r, bd);
                bh[2 * p][0] = r[0]; bh[2 * p][1] = r[1];
                bh[2 * p + 1][0] = r[2]; bh[2 * p + 1][1] = r[3];
                ldm4(r, bd + TILE_B);
                bl[2 * p][0] = r[0]; bl[2 * p][1] = r[1];
                bl[2 * p + 1][0] = r[2]; bl[2 * p + 1][1] = r[3];
            }
#pragma unroll
            for (int mf = 0; mf < 4; mf++)
#pragma unroll
                for (int nf = 0; nf < 4; nf++) {
                    mma_bf16(acc[mf][nf], ah[mf], bh[nf]);
                    mma_bf16(acc[mf][nf], ah[mf], bl[nf]);
                    mma_bf16(acc[mf][nf], al[mf], bh[nf]);
                }
        }
    }
#undef LOAD_STAGE

    // ---- epilogue ----
    const int gq = lane >> 2, tg = lane & 3;
#pragma unroll
    for (int mf = 0; mf < 4; mf++)
#pragma unroll
        for (int nf = 0; nf < 4; nf++) {
            const long row = m0 + moff + mf * 16 + gq;
            const long col = n0 + noff + nf * 8 + tg * 2;
            float v0 = alpha * acc[mf][nf][0];
            float v1 = alpha * acc[mf][nf][1];
            float v2 = alpha * acc[mf][nf][2];
            float v3 = alpha * acc[mf][nf][3];
            if (MODE == 0) {
                float2 p0 = {v0, v1}, p1 = {v2, v3};
                *reinterpret_cast<float2*>(C + coff + row * ldc + col)       = p0;
                *reinterpret_cast<float2*>(C + coff + (row + 8) * ldc + col) = p1;
            } else {
                __nv_bfloat16 h0, l0, h1, l1, h2, l2, h3, l3;
                split2(v0, h0, l0); split2(v1, h1, l1);
                split2(v2, h2, l2); split2(v3, h3, l3);
                uint32_t hp0 = (uint32_t)__bfloat16_as_ushort(h1) << 16 | __bfloat16_as_ushort(h0);
                uint32_t lp0 = (uint32_t)__bfloat16_as_ushort(l1) << 16 | __bfloat16_as_ushort(l0);
                uint32_t hp1 = (uint32_t)__bfloat16_as_ushort(h3) << 16 | __bfloat16_as_ushort(h2);
                uint32_t lp1 = (uint32_t)__bfloat16_as_ushort(l3) << 16 | __bfloat16_as_ushort(l2);
                *reinterpret_cast<uint32_t*>(Chi + coff + row * ldc + col)       = hp0;
                *reinterpret_cast<uint32_t*>(Clo + coff + row * ldc + col)       = lp0;
                *reinterpret_cast<uint32_t*>(Chi + coff + (row + 8) * ldc + col) = hp1;
                *reinterpret_cast<uint32_t*>(Clo + coff + (row + 8) * ldc + col) = lp1;
            }
        }
}

// ======================= helper kernels =====================================
__global__ __launch_bounds__(256)
void split_arr(const float4* __restrict__ s, uint2* __restrict__ hi,
               uint2* __restrict__ lo, int n4)
{
    int i = blockIdx.x * 256 + threadIdx.x;
    if (i >= n4) return;
    float4 v = s[i];
    __nv_bfloat16 h[4], l[4];
    split2(v.x, h[0], l[0]);
    split2(v.y, h[1], l[1]);
    split2(v.z, h[2], l[2]);
    split2(v.w, h[3], l[3]);
    hi[i] = *reinterpret_cast<uint2*>(h);
    lo[i] = *reinterpret_cast<uint2*>(l);
}

// W [Z,512,512] fp32 -> WT hi/lo [Z,512,512] with per-z transpose
__global__ __launch_bounds__(256)
void transpose_split_w(const float* __restrict__ src,
                       __nv_bfloat16* __restrict__ hi, __nv_bfloat16* __restrict__ lo)
{
    __shared__ float t[32][33];
    const int z = blockIdx.z;
    const int e0 = blockIdx.y * 32, d0 = blockIdx.x * 32;
    const int tx = threadIdx.x & 31, ty = threadIdx.x >> 5;
    const float* s = src + (long)z * D_ * D_;
#pragma unroll
    for (int r = 0; r < 32; r += 8)
        t[ty + r][tx] = s[(long)(e0 + ty + r) * D_ + d0 + tx];
    __syncthreads();
    const long base = (long)z * D_ * D_;
#pragma unroll
    for (int r = 0; r < 32; r += 8) {
        float x = t[tx][ty + r];             // = src[z, e0+tx, d0+ty+r]
        __nv_bfloat16 h, l;
        split2(x, h, l);
        long o = base + (long)(d0 + ty + r) * D_ + e0 + tx;
        hi[o] = h; lo[o] = l;
    }
}

// Wo [D, H*D] -> Wo'[h][e,f] = Wo[e, (f/64)*512 + h*64 + (f%64)], split hi/lo
__global__ __launch_bounds__(256)
void wo_permute_split(const float* __restrict__ Wo,
                      __nv_bfloat16* __restrict__ hi, __nv_bfloat16* __restrict__ lo)
{
    long idx = (long)blockIdx.x * 256 + threadIdx.x;   // over H*D*D = 2M
    int f = (int)(idx & 511);
    int e = (int)((idx >> 9) & 511);
    int h = (int)(idx >> 18);
    float x = Wo[(long)e * (H_ * D_) + (f >> 6) * 512 + h * 64 + (f & 63)];
    __nv_bfloat16 hb, lb;
    split2(x, hb, lb);
    hi[idx] = hb; lo[idx] = lb;
}

// softmax over rows of 2048 in place (fp32, [b,h,l,m]) + bf16 hi/lo in [b,l,h,m]
__global__ __launch_bounds__(256)
void softmax_split(float* __restrict__ data,
                   __nv_bfloat16* __restrict__ hi, __nv_bfloat16* __restrict__ lo)
{
    const int r = blockIdx.x;                 // (b*H + h)*L + l
    const int b = r >> 14;                    // / (H*L)
    const int h = (r >> 11) & (H_ - 1);
    const int l = r & (L_ - 1);
    float* p = data + (long)r * L_;
    const long ob = (((long)b * L_ + l) * H_ + h) * L_;
    const int tid = threadIdx.x;

    float vals[8];
    float vmax = -1e30f;
#pragma unroll
    for (int i = 0; i < 8; i++) { vals[i] = p[tid + i * 256]; vmax = fmaxf(vmax, vals[i]); }
#pragma unroll
    for (int o = 16; o > 0; o >>= 1) vmax = fmaxf(vmax, __shfl_xor_sync(0xFFFFFFFFu, vmax, o));

    __shared__ float smax[8], ssum[8];
    if ((tid & 31) == 0) smax[tid >> 5] = vmax;
    __syncthreads();
    float m = smax[0];
#pragma unroll
    for (int i = 1; i < 8; i++) m = fmaxf(m, smax[i]);

    float sum = 0.f;
#pragma unroll
    for (int i = 0; i < 8; i++) { vals[i] = __expf(vals[i] - m); sum += vals[i]; }
#pragma unroll
    for (int o = 16; o > 0; o >>= 1) sum += __shfl_xor_sync(0xFFFFFFFFu, sum, o);
    if ((tid & 31) == 0) ssum[tid >> 5] = sum;
    __syncthreads();
    float tot = 0.f;
#pragma unroll
    for (int i = 0; i < 8; i++) tot += ssum[i];
    const float inv = 1.f / tot;
#pragma unroll
    for (int i = 0; i < 8; i++) {
        float y = vals[i] * inv;
        p[tid + i * 256] = y;
        __nv_bfloat16 hh, ll;
        split2(y, hh, ll);
        hi[ob + tid + i * 256] = hh;
        lo[ob + tid + i * 256] = ll;
    }
}

// ======================= launch =============================================
extern "C" void kernel_launch(void* const* d_in, const int* in_sizes, int n_in,
                              void* d_out, int out_size)
{
    const float* q  = (const float*)d_in[0];
    const float* k  = (const float*)d_in[1];
    const float* v  = (const float*)d_in[2];
    const float* Wq = (const float*)d_in[3];
    const float* Wk = (const float*)d_in[4];
    const float* Wv = (const float*)d_in[5];
    const float* Wo = (const float*)d_in[6];

    float* out  = (float*)d_out;
    float* attn = out + (long)B_ * L_ * D_;

    static bool attr_done = false;
    if (!attr_done) {
        cudaFuncSetAttribute(mma_gemm<0>, cudaFuncAttributeMaxDynamicSharedMemorySize, SMEM_T);
        cudaFuncSetAttribute(mma_gemm<1>, cudaFuncAttributeMaxDynamicSharedMemorySize, SMEM_T);
        attr_done = true;
    }

#define SYM(p, s) cudaGetSymbolAddress((void**)&p, s)
    __nv_bfloat16 *q_hi, *q_lo, *k_hi, *k_lo, *v_hi, *v_lo;
    __nv_bfloat16 *WqT_hi, *WqT_lo, *WkT_hi, *WkT_lo, *WvT_hi, *WvT_lo, *Wop_hi, *Wop_lo;
    __nv_bfloat16 *MT_hi, *MT_lo, *P_hi, *P_lo;
    __nv_bfloat16 *t_hi, *t_lo, *ZT_hi, *ZT_lo, *at_hi, *at_lo;
    SYM(q_hi, g_q_hi);  SYM(q_lo, g_q_lo);
    SYM(k_hi, g_k_hi);  SYM(k_lo, g_k_lo);
    SYM(v_hi, g_v_hi);  SYM(v_lo, g_v_lo);
    SYM(WqT_hi, g_WqT_hi); SYM(WqT_lo, g_WqT_lo);
    SYM(WkT_hi, g_WkT_hi); SYM(WkT_lo, g_WkT_lo);
    SYM(WvT_hi, g_WvT_hi); SYM(WvT_lo, g_WvT_lo);
    SYM(Wop_hi, g_Wop_hi); SYM(Wop_lo, g_Wop_lo);
    SYM(MT_hi, g_MT_hi);   SYM(MT_lo, g_MT_lo);
    SYM(P_hi, g_P_hi);     SYM(P_lo, g_P_lo);
    SYM(t_hi, g_t_hi);     SYM(t_lo, g_t_lo);
    SYM(ZT_hi, g_ZT_hi);   SYM(ZT_lo, g_ZT_lo);
    SYM(at_hi, g_at_hi);   SYM(at_lo, g_at_lo);
#undef SYM

    const long sLD = (long)L_ * D_;
    const long sLL = (long)L_ * L_;
    const long sDD = (long)D_ * D_;
    const float inv_sqrt_d = 1.0f / sqrtf((float)D_);

    dim3 blk(256);
    const int n4_in = (B_ * L_ * D_) / 4;

    // 0) split q,k,v to bf16 hi/lo; transpose-split Wq,Wk,Wv; permute-split Wo
    split_arr<<<(n4_in + 255) / 256, blk>>>((const float4*)q, (uint2*)q_hi, (uint2*)q_lo, n4_in);
    split_arr<<<(n4_in + 255) / 256, blk>>>((const float4*)k, (uint2*)k_hi, (uint2*)k_lo, n4_in);
    split_arr<<<(n4_in + 255) / 256, blk>>>((const float4*)v, (uint2*)v_hi, (uint2*)v_lo, n4_in);
    dim3 gtw(D_ / 32, D_ / 32, H_);
    transpose_split_w<<<gtw, blk>>>(Wq, WqT_hi, WqT_lo);
    transpose_split_w<<<gtw, blk>>>(Wk, WkT_hi, WkT_lo);
    transpose_split_w<<<gtw, blk>>>(Wv, WvT_hi, WvT_lo);
    wo_permute_split<<<(H_ * D_ * D_) / 256, blk>>>(Wo, Wop_hi, Wop_lo);

    // 1) MT[h] = WkT[h] @ WqT[h]^T  (MT[d',d] = sum_e Wk[e,d'] Wq[e,d])
    dim3 gW(D_ / 128, D_ / 128, H_);
    mma_gemm<1><<<gW, blk, SMEM_T>>>(WkT_hi, WkT_lo, WqT_hi, WqT_lo,
        nullptr, MT_hi, MT_lo, D_, D_, sDD, sDD, 1, H_, 1, H_, 1, sDD, 1, 0, 1.0f);

    // 2) P[h] = Wo'[h] @ WvT[h]^T  (P[e,d] = sum_f Wo'[e,f] Wv[f,d])
    mma_gemm<1><<<gW, blk, SMEM_T>>>(Wop_hi, Wop_lo, WvT_hi, WvT_lo,
        nullptr, P_hi, P_lo, D_, D_, sDD, sDD, 1, H_, 1, H_, 1, sDD, 1, 0, 1.0f);

    // 3) t[b,h] = q[b] @ MT[h]^T  [L,D]
    dim3 gt(D_ / 128, L_ / 128, B_ * H_);
    mma_gemm<1><<<gt, blk, SMEM_T>>>(q_hi, q_lo, MT_hi, MT_lo,
        nullptr, t_hi, t_lo, D_, D_, sLD, sDD, H_, B_, 1, H_, 1, sLD, 1, 0, 1.0f);

    // 4) scores[b,h] = t[b,h] @ k[b]^T / sqrt(D) -> attn fp32 in d_out
    dim3 gsc(L_ / 128, L_ / 128, B_ * H_);
    mma_gemm<0><<<gsc, blk, SMEM_T>>>(t_hi, t_lo, k_hi, k_lo,
        attn, nullptr, nullptr, D_, L_, sLD, sLD, 1, B_ * H_, H_, B_, 1, sLL, 1, 0, inv_sqrt_d);

    // 5) ZT'[b, e, h, m] = P[h] @ v[b]^T   (ldc = H*L)
    dim3 gz(L_ / 128, D_ / 128, B_ * H_);
    mma_gemm<1><<<gz, blk, SMEM_T>>>(P_hi, P_lo, v_hi, v_lo,
        nullptr, ZT_hi, ZT_lo, D_, H_ * L_, sDD, sLD, 1, H_, H_, B_,
        H_, (long)D_ * H_ * L_, H_, (long)L_, 1.0f);

    // 6) softmax in place + bf16 hi/lo in permuted [b,l,h,m] layout
    softmax_split<<<B_ * H_ * L_, blk>>>(attn, at_hi, at_lo);

    // 7) out[b] = at'[b] [L, H*L] @ ZT'[b] [D, H*L]^T  (K = H*L)
    dim3 go(D_ / 128, L_ / 128, B_);
    mma_gemm<0><<<go, blk, SMEM_T>>>(at_hi, at_lo, ZT_hi, ZT_lo,
        out, nullptr, nullptr, H_ * L_, D_, (long)L_ * H_ * L_, (long)D_ * H_ * L_,
        1, B_, 1, B_, 1, sLD, 1, 0, 1.0f);
}